// round 14
// baseline (speedup 1.0000x reference)
#include <cuda_runtime.h>
#include <cstdint>

// Problem constants:
//   B=8, H=8, L=1024, D=64, K=49
//   x:  (B,H,L,D) fp32   = d_in[0]
//   W:  (H,D,K)   fp32   = d_in[1]
//   rp: (L,L)     int32  = d_in[2]
//   out:(B,H,L,L) fp32
// Separable structure: i = row_i*32 + col_i, j = rj*32 + cj,
//   rp[i][j] = 7*(pw(row_i-rj)+3) + (pw(col_i-cj)+3), pw in [-3,3].
#define BB 8
#define HH 8
#define LL 1024
#define DD 64
#define KK 49
#define BH (BB*HH)

#define IPB 8              // i-rows per block (one per warp)
#define XP 10              // padded xst row: 8 b's + 2 pad (rows 40B-aligned)
#define WSLOT (DD * XP)    // 640 floats: per-warp region in the shared overlay

// ---------------------------------------------------------------------------
// Fused kernel v11 = v10 with the gather vectorized to STG.128.
//   Lane owns a quad of 4 consecutive j: cj-quad = (lane&7)*4, rj-subslot =
//   lane>>3. Per rjg iteration a warp covers j = rjg*128..+127 (512 B,
//   perfectly coalesced STG.128). Gather per warp-row: 8 shfl + 256 LDS.32
//   + 64 STG.128 (was 32 shfl + 256 LDS + 256 STG.32).
//
// Block (i-group, h): 8 warps; warp w owns i = i0+w and ALL 8 b's.
// grid: (L/8, H) = (128, 8), block: 256.
// ---------------------------------------------------------------------------
__global__ __launch_bounds__(256, 5) void irpe_fused11_kernel(
    const float* __restrict__ x, const float* __restrict__ W,
    const int* __restrict__ rp, float* __restrict__ out)
{
    const int h    = blockIdx.y;
    const int i0   = blockIdx.x * IPB;
    const int tid  = threadIdx.x;
    const int w    = tid >> 5;
    const int lane = tid & 31;
    const int i    = i0 + w;
    const int row_i = i >> 5;
    const int col_i = i & 31;

    __shared__ float Ws[DD * KK + 32];      // 12.7 KB, natural layout
    __shared__ float buf[IPB * WSLOT];      // 20 KB: xst, later aliased as lts

    // Separable index extraction.
    //   c4: the 4 cidx values of this lane's cj-quad (cj = (lane&7)*4 .. +3)
    //   rbase: 7*r for rj = lane
    int4 c4 = *(const int4*)(rp + (size_t)i * LL + row_i * 32 + (lane & 7) * 4);
    c4.x -= 21; c4.y -= 21; c4.z -= 21; c4.w -= 21;          // in [0,6] + ...
    const int rbase = rp[(size_t)i * LL + lane * 32 + col_i] - 3;   // 7*r

    // Stage W[h]: direct coalesced copy
    {
        const float* Wh = W + (size_t)h * DD * KK;
        #pragma unroll
        for (int t = tid; t < DD * KK; t += 256)
            Ws[t] = Wh[t];
    }

    // Stage x transposed with padded rows: buf[ww*640 + d*10 + b]
    #pragma unroll
    for (int t = tid; t < IPB * BB * (DD / 4); t += 256) {
        const int ww = t >> 7;
        const int b  = (t >> 4) & 7;
        const int q  = t & 15;
        float4 v = *(const float4*)(x + ((size_t)(b * HH + h) * LL + i0 + ww) * DD + q * 4);
        float* dst = buf + ww * WSLOT + (q * 4) * XP + b;
        dst[0 * XP] = v.x;
        dst[1 * XP] = v.y;
        dst[2 * XP] = v.z;
        dst[3 * XP] = v.w;
    }
    __syncthreads();

    // Compute lt for all 8 b (b-pairs packed in f32x2)
    unsigned long long acc[8];
    #pragma unroll
    for (int j = 0; j < 8; j++) acc[j] = 0ull;

    const float* xw = buf + w * WSLOT;
    #pragma unroll 16
    for (int d = 0; d < DD; d++) {
        const float w0 = Ws[d * KK + lane];            // conflict-free
        const float w1 = Ws[d * KK + 32 + lane];       // junk lanes>=17, discarded
        unsigned long long wp0, wp1;
        asm("mov.b64 %0, {%1, %1};" : "=l"(wp0) : "f"(w0));
        asm("mov.b64 %0, {%1, %1};" : "=l"(wp1) : "f"(w1));
        const float* xr = xw + d * XP;                 // 8B-aligned row
        const unsigned long long xa = *(const unsigned long long*)(xr);
        const unsigned long long xb = *(const unsigned long long*)(xr + 2);
        const unsigned long long xc = *(const unsigned long long*)(xr + 4);
        const unsigned long long xd = *(const unsigned long long*)(xr + 6);
        asm("fma.rn.f32x2 %0, %1, %2, %0;" : "+l"(acc[0]) : "l"(xa), "l"(wp0));
        asm("fma.rn.f32x2 %0, %1, %2, %0;" : "+l"(acc[1]) : "l"(xb), "l"(wp0));
        asm("fma.rn.f32x2 %0, %1, %2, %0;" : "+l"(acc[2]) : "l"(xc), "l"(wp0));
        asm("fma.rn.f32x2 %0, %1, %2, %0;" : "+l"(acc[3]) : "l"(xd), "l"(wp0));
        asm("fma.rn.f32x2 %0, %1, %2, %0;" : "+l"(acc[4]) : "l"(xa), "l"(wp1));
        asm("fma.rn.f32x2 %0, %1, %2, %0;" : "+l"(acc[5]) : "l"(xb), "l"(wp1));
        asm("fma.rn.f32x2 %0, %1, %2, %0;" : "+l"(acc[6]) : "l"(xc), "l"(wp1));
        asm("fma.rn.f32x2 %0, %1, %2, %0;" : "+l"(acc[7]) : "l"(xd), "l"(wp1));
    }

    // Spill lt into the SAME warp-private region (xst now dead): lw[b*49+k]
    float* lw = buf + w * WSLOT;
    __syncwarp();   // all lanes of this warp done reading xst
    #pragma unroll
    for (int bp = 0; bp < 4; bp++) {
        float lo, hi;
        asm("mov.b64 {%0, %1}, %2;" : "=f"(lo), "=f"(hi) : "l"(acc[bp]));
        lw[(2 * bp)     * KK + lane] = lo;
        lw[(2 * bp + 1) * KK + lane] = hi;
        if (lane < KK - 32) {
            asm("mov.b64 {%0, %1}, %2;" : "=f"(lo), "=f"(hi) : "l"(acc[4 + bp]));
            lw[(2 * bp)     * KK + 32 + lane] = lo;
            lw[(2 * bp + 1) * KK + 32 + lane] = hi;
        }
    }
    __syncwarp();

    // Gather + STG.128 streaming stores.
    // Lane quad: j = rj*32 + (lane&7)*4 + {0..3},  rj = rjg*4 + (lane>>3).
    // out[b*8+h][i][j] = lw[b*49 + rbase(rj) + c4.{x..w}]
    const int sub = lane >> 3;                 // rj sub-slot 0..3
    const int q8  = lane & 7;                  // cj-quad id
    float* ob = out + ((size_t)h * LL + i) * LL;    // b=0 row base
    #pragma unroll
    for (int rjg = 0; rjg < 8; rjg++) {
        const int rb = __shfl_sync(0xffffffffu, rbase, rjg * 4 + sub);
        const float* src = lw + rb;
        const int fidx = rjg * 32 + sub * 8 + q8;    // float4 index in row
        #pragma unroll
        for (int b = 0; b < BB; b++) {
            const float* sb = src + b * KK;
            float4 v;
            v.x = sb[c4.x];
            v.y = sb[c4.y];
            v.z = sb[c4.z];
            v.w = sb[c4.w];
            __stcs((float4*)(ob + (size_t)b * (HH * LL * LL)) + fidx, v);
        }
    }
}

// ---------------------------------------------------------------------------
extern "C" void kernel_launch(void* const* d_in, const int* in_sizes, int n_in,
                              void* d_out, int out_size)
{
    const float* x  = (const float*)d_in[0];
    const float* W  = (const float*)d_in[1];
    const int*   rp = (const int*)d_in[2];
    float*       out = (float*)d_out;

    dim3 grid(LL / IPB, HH);
    irpe_fused11_kernel<<<grid, 256>>>(x, W, rp, out);
}